// round 2
// baseline (speedup 1.0000x reference)
#include <cuda_runtime.h>

#define NA 256
#define NM 16
#define NT 80
#define NO 64

// Dynamic smem (floats):
//   s_cox [NO*NT], s_coy [NO*NT], s_cohw [NO*NT]  compacted valid others, [slot][t]
//   s_px  [NM*NT], s_py  [NM*NT]                  masked ego preds
static const int SMEM_FLOATS = 3 * NO * NT + 2 * NM * NT;

__global__ __launch_bounds__(256) void path_reward_collision_kernel(
    const float* __restrict__ targets,          // (A,T,2)
    const int*   __restrict__ target_mask,      // (A,T)
    const float* __restrict__ traj_preds,       // (A,M,T,4)
    const float* __restrict__ agent_fut_width,  // (A,T)
    const float* __restrict__ other_trajs,      // (A,O,T,2)
    const int*   __restrict__ other_masks,      // (A,O,T)
    const float* __restrict__ other_widths,     // (A,O,T)
    float*       __restrict__ out)              // (3,A,M)
{
    extern __shared__ float sm[];
    float* s_cox = sm;                   // [slot][t]
    float* s_coy = s_cox + NO * NT;
    float* s_cohw= s_coy + NO * NT;
    float* s_px  = s_cohw+ NO * NT;      // [NM][NT]
    float* s_py  = s_px  + NM * NT;

    __shared__ float s_tm[NT], s_hwi[NT], s_tgx[NT], s_tgy[NT];
    __shared__ int   s_cnt[NT];
    __shared__ float l2sum[NM];
    __shared__ int   ccnt[NM];

    const int a   = blockIdx.x;
    const int tid = threadIdx.x;

    if (tid < NM) ccnt[tid] = 0;
    if (tid < NT) s_cnt[tid] = 0;

    // Per-timestep ego data: mask, half-width (invalid -> -1), masked target.
    for (int t = tid; t < NT; t += 256) {
        float tm = (float)target_mask[a * NT + t];
        s_tm[t]  = tm;
        s_hwi[t] = (tm > 0.0f) ? 0.5f * agent_fut_width[a * NT + t] : -1.0f;
        float2 tg = ((const float2*)targets)[a * NT + t];
        s_tgx[t] = __fmul_rn(tm, tg.x);
        s_tgy[t] = __fmul_rn(tm, tg.y);
    }
    __syncthreads();  // s_tm needed for pred masking; s_cnt zeroed before compaction

    // Masked predictions (xy of the 4-vector), [m][t].
    for (int i = tid; i < NM * NT; i += 256) {
        int t = i % NT;
        float4 p = ((const float4*)traj_preds)[a * NM * NT + i];
        float tm = s_tm[t];
        s_px[i] = __fmul_rn(tm, p.x);
        s_py[i] = __fmul_rn(tm, p.y);
    }

    // Compact valid others per timestep into [slot][t] layout.
    for (int i = tid; i < NO * NT; i += 256) {
        int t = i % NT;                      // i = o*NT + t
        int g = a * NO * NT + i;
        if (other_masks[g] > 0) {
            int slot = atomicAdd(&s_cnt[t], 1);
            float2 xy = ((const float2*)other_trajs)[g];
            s_cox [slot * NT + t] = xy.x;
            s_coy [slot * NT + t] = xy.y;
            s_cohw[slot * NT + t] = 0.5f * other_widths[g];
        }
    }
    __syncthreads();

    // L2 path: 16 threads, one mode each, serial over T (deterministic order).
    if (tid < NM) {
        const float* px = s_px + tid * NT;
        const float* py = s_py + tid * NT;
        float acc = 0.0f;
        for (int t = 0; t < NT; t++) {
            float dx = __fsub_rn(px[t], s_tgx[t]);
            float dy = __fsub_rn(py[t], s_tgy[t]);
            float s  = __fadd_rn(__fmul_rn(dx, dx), __fmul_rn(dy, dy));
            if (s > 0.0f) acc = __fadd_rn(acc, __fsqrt_rn(s));
        }
        l2sum[tid] = acc;
    }

    // Collision path: for each (m,t) pair, ANY valid other within radius?
    // collision[m] = number of timesteps with a hit.
    #pragma unroll 1
    for (int k = 0; k < (NM * NT) / 256; k++) {   // 1280/256 = 5
        int p = tid + k * 256;
        int m = p / NT;
        int t = p - m * NT;
        float hwi = s_hwi[t];
        if (hwi < 0.0f) continue;                 // ego invalid at t -> no collision
        float px = s_px[m * NT + t];
        float py = s_py[m * NT + t];
        int n = s_cnt[t];
        int hit = 0;
        for (int o = 0; o < n; o++) {
            float r  = __fadd_rn(hwi, s_cohw[o * NT + t]);   // r in [0,2]
            float dx = __fsub_rn(px, s_cox[o * NT + t]);
            float dy = __fsub_rn(py, s_coy[o * NT + t]);
            float d2 = __fadd_rn(__fmul_rn(dx, dx), __fmul_rn(dy, dy));
            // conservative squared filter, then exact correctly-rounded test
            if (d2 <= __fmul_rn(r, r) * 1.00001f) {
                if (__fsqrt_rn(d2) <= r) { hit = 1; break; }
            }
        }
        if (hit) atomicAdd(&ccnt[m], 1);          // integer -> deterministic
    }
    __syncthreads();

    if (tid < NM) {
        float l2p = __fsub_rn(8.0f, l2sum[tid]);        // -(total_l2 - OFFSET)
        float cp  = __fmul_rn(-100.0f, (float)ccnt[tid]);
        int idx = a * NM + tid;
        out[idx]                = __fadd_rn(l2p, cp);   // total
        out[NA * NM + idx]      = cp;                   // collision_penalty
        out[2 * NA * NM + idx]  = l2p;                  // l2_penalty
    }
}

extern "C" void kernel_launch(void* const* d_in, const int* in_sizes, int n_in,
                              void* d_out, int out_size) {
    const float* targets         = (const float*)d_in[0];
    const int*   target_mask     = (const int*)  d_in[1];
    const float* traj_preds      = (const float*)d_in[2];
    // d_in[3] = mode_probs (unused by reference)
    const float* agent_fut_width = (const float*)d_in[4];
    const float* other_trajs     = (const float*)d_in[5];
    const int*   other_masks     = (const int*)  d_in[6];
    const float* other_widths    = (const float*)d_in[7];
    float* out = (float*)d_out;

    const int smem_bytes = SMEM_FLOATS * (int)sizeof(float);  // 71680
    cudaFuncSetAttribute(path_reward_collision_kernel,
                         cudaFuncAttributeMaxDynamicSharedMemorySize, smem_bytes);
    path_reward_collision_kernel<<<NA, 256, smem_bytes>>>(
        targets, target_mask, traj_preds, agent_fut_width,
        other_trajs, other_masks, other_widths, out);
}

// round 3
// speedup vs baseline: 1.6702x; 1.6702x over previous
#include <cuda_runtime.h>

#define NA 256
#define NM 16
#define NT 80
#define NO 64
#define BLK 512

// Dynamic smem:
//   s_o4 [NO*NT] float4  compacted valid others (x, y, halfwidth, 0), [slot][t]
//   s_px [NM*NT], s_py [NM*NT]  masked ego preds
static const int SMEM_BYTES = NO * NT * 16 + 2 * NM * NT * 4;   // 92160

__global__ __launch_bounds__(BLK) void path_reward_collision_kernel(
    const float* __restrict__ targets,          // (A,T,2)
    const int*   __restrict__ target_mask,      // (A,T)
    const float* __restrict__ traj_preds,       // (A,M,T,4)
    const float* __restrict__ agent_fut_width,  // (A,T)
    const float* __restrict__ other_trajs,      // (A,O,T,2)
    const int*   __restrict__ other_masks,      // (A,O,T)
    const float* __restrict__ other_widths,     // (A,O,T)
    float*       __restrict__ out)              // (3,A,M)
{
    extern __shared__ float4 s_o4[];            // [slot][t]
    float* s_px = (float*)(s_o4 + NO * NT);     // [NM][NT]
    float* s_py = s_px + NM * NT;

    __shared__ float s_tm[NT], s_hwi[NT], s_tgx[NT], s_tgy[NT];
    __shared__ int   s_cnt[NT];
    __shared__ int   ccnt[NM];

    const int a   = blockIdx.x;
    const int tid = threadIdx.x;

    if (tid < NM) ccnt[tid] = 0;
    if (tid < NT) s_cnt[tid] = 0;

    // Per-timestep ego data: mask, half-width (invalid -> -1), masked target.
    if (tid < NT) {
        int t = tid;
        float tm = (float)target_mask[a * NT + t];
        s_tm[t]  = tm;
        s_hwi[t] = (tm > 0.0f) ? 0.5f * agent_fut_width[a * NT + t] : -1.0f;
        float2 tg = ((const float2*)targets)[a * NT + t];
        s_tgx[t] = __fmul_rn(tm, tg.x);
        s_tgy[t] = __fmul_rn(tm, tg.y);
    }
    __syncthreads();   // s_tm ready; s_cnt zeroed

    // Masked predictions (xy of the 4-vector), [m][t].
    for (int i = tid; i < NM * NT; i += BLK) {
        int t = i % NT;
        float4 p = ((const float4*)traj_preds)[a * NM * NT + i];
        float tm = s_tm[t];
        s_px[i] = __fmul_rn(tm, p.x);
        s_py[i] = __fmul_rn(tm, p.y);
    }

    // Compact valid others per timestep into [slot][t] float4 layout.
    for (int i = tid; i < NO * NT; i += BLK) {
        int t = i % NT;                      // i = o*NT + t
        int g = a * NO * NT + i;
        if (other_masks[g] > 0) {
            int slot = atomicAdd(&s_cnt[t], 1);
            float2 xy = ((const float2*)other_trajs)[g];
            s_o4[slot * NT + t] = make_float4(xy.x, xy.y, 0.5f * other_widths[g], 0.0f);
        }
    }
    __syncthreads();

    // L2 path: warp w (<16) handles mode w. Lane sums t = lane, lane+32, lane+64,
    // then fixed-order shuffle tree -> deterministic.
    {
        int wid = tid >> 5, lane = tid & 31;
        if (wid < NM) {
            const float* px = s_px + wid * NT;
            const float* py = s_py + wid * NT;
            float acc = 0.0f;
            #pragma unroll
            for (int k = 0; k < 3; k++) {
                int t = lane + k * 32;
                if (t < NT) {
                    float dx = __fsub_rn(px[t], s_tgx[t]);
                    float dy = __fsub_rn(py[t], s_tgy[t]);
                    float s  = __fadd_rn(__fmul_rn(dx, dx), __fmul_rn(dy, dy));
                    if (s > 0.0f) acc = __fadd_rn(acc, __fsqrt_rn(s));
                }
            }
            #pragma unroll
            for (int off = 16; off > 0; off >>= 1)
                acc = __fadd_rn(acc, __shfl_xor_sync(0xffffffffu, acc, off));
            if (lane == 0) {
                float l2p = __fsub_rn(8.0f, acc);       // -(total_l2 - OFFSET)
                out[2 * NA * NM + a * NM + wid] = l2p;  // l2_penalty (total written later)
            }
        }
    }

    // Collision path: task = (m,t); ANY compacted other within radius?
    #pragma unroll 1
    for (int p = tid; p < NM * NT; p += BLK) {
        int m = p / NT;
        int t = p - m * NT;
        float hwi = s_hwi[t];
        if (hwi < 0.0f) continue;                 // ego invalid at t
        float px = s_px[m * NT + t];
        float py = s_py[m * NT + t];
        const float4* base = s_o4 + t;
        int n = s_cnt[t];
        int hit = 0;
        int o = 0;
        #pragma unroll 1
        for (; o + 4 <= n; o += 4) {
            float4 c0 = base[(o + 0) * NT];
            float4 c1 = base[(o + 1) * NT];
            float4 c2 = base[(o + 2) * NT];
            float4 c3 = base[(o + 3) * NT];
            float dx0 = __fsub_rn(px, c0.x), dy0 = __fsub_rn(py, c0.y);
            float dx1 = __fsub_rn(px, c1.x), dy1 = __fsub_rn(py, c1.y);
            float dx2 = __fsub_rn(px, c2.x), dy2 = __fsub_rn(py, c2.y);
            float dx3 = __fsub_rn(px, c3.x), dy3 = __fsub_rn(py, c3.y);
            float d20 = __fadd_rn(__fmul_rn(dx0, dx0), __fmul_rn(dy0, dy0));
            float d21 = __fadd_rn(__fmul_rn(dx1, dx1), __fmul_rn(dy1, dy1));
            float d22 = __fadd_rn(__fmul_rn(dx2, dx2), __fmul_rn(dy2, dy2));
            float d23 = __fadd_rn(__fmul_rn(dx3, dx3), __fmul_rn(dy3, dy3));
            float r0 = __fadd_rn(hwi, c0.z), r1 = __fadd_rn(hwi, c1.z);
            float r2 = __fadd_rn(hwi, c2.z), r3 = __fadd_rn(hwi, c3.z);
            // conservative squared filter (r <= 2, no overflow)
            bool f0 = d20 <= __fmul_rn(r0, r0) * 1.00001f;
            bool f1 = d21 <= __fmul_rn(r1, r1) * 1.00001f;
            bool f2 = d22 <= __fmul_rn(r2, r2) * 1.00001f;
            bool f3 = d23 <= __fmul_rn(r3, r3) * 1.00001f;
            if (f0 | f1 | f2 | f3) {              // rare: exact correctly-rounded test
                if ((__fsqrt_rn(d20) <= r0) | (__fsqrt_rn(d21) <= r1) |
                    (__fsqrt_rn(d22) <= r2) | (__fsqrt_rn(d23) <= r3)) { hit = 1; break; }
            }
        }
        if (!hit) {
            for (; o < n; o++) {
                float4 c = base[o * NT];
                float dx = __fsub_rn(px, c.x), dy = __fsub_rn(py, c.y);
                float d2 = __fadd_rn(__fmul_rn(dx, dx), __fmul_rn(dy, dy));
                float r  = __fadd_rn(hwi, c.z);
                if (d2 <= __fmul_rn(r, r) * 1.00001f) {
                    if (__fsqrt_rn(d2) <= r) { hit = 1; break; }
                }
            }
        }
        if (hit) atomicAdd(&ccnt[m], 1);          // integer -> deterministic
    }
    __syncthreads();

    if (tid < NM) {
        int idx = a * NM + tid;
        float l2p = out[2 * NA * NM + idx];
        float cp  = __fmul_rn(-100.0f, (float)ccnt[tid]);
        out[idx]           = __fadd_rn(l2p, cp);   // total
        out[NA * NM + idx] = cp;                   // collision_penalty
    }
}

extern "C" void kernel_launch(void* const* d_in, const int* in_sizes, int n_in,
                              void* d_out, int out_size) {
    const float* targets         = (const float*)d_in[0];
    const int*   target_mask     = (const int*)  d_in[1];
    const float* traj_preds      = (const float*)d_in[2];
    // d_in[3] = mode_probs (unused by reference)
    const float* agent_fut_width = (const float*)d_in[4];
    const float* other_trajs     = (const float*)d_in[5];
    const int*   other_masks     = (const int*)  d_in[6];
    const float* other_widths    = (const float*)d_in[7];
    float* out = (float*)d_out;

    cudaFuncSetAttribute(path_reward_collision_kernel,
                         cudaFuncAttributeMaxDynamicSharedMemorySize, SMEM_BYTES);
    path_reward_collision_kernel<<<NA, BLK, SMEM_BYTES>>>(
        targets, target_mask, traj_preds, agent_fut_width,
        other_trajs, other_masks, other_widths, out);
}

// round 4
// speedup vs baseline: 1.6905x; 1.0122x over previous
#include <cuda_runtime.h>

#define NA 256
#define NM 16
#define NT 80
#define NO 64
#define BLK 1024

// Dynamic smem:
//   s_o4 [NO*NT] float4  compacted valid others (x, y, halfwidth, 0), [slot][t]
//   s_px [NM*NT], s_py [NM*NT]  masked ego preds
static const int SMEM_BYTES = NO * NT * 16 + 2 * NM * NT * 4;   // 92160

__global__ __launch_bounds__(BLK, 2) void path_reward_collision_kernel(
    const float* __restrict__ targets,          // (A,T,2)
    const int*   __restrict__ target_mask,      // (A,T)
    const float* __restrict__ traj_preds,       // (A,M,T,4)
    const float* __restrict__ agent_fut_width,  // (A,T)
    const float* __restrict__ other_trajs,      // (A,O,T,2)
    const int*   __restrict__ other_masks,      // (A,O,T)
    const float* __restrict__ other_widths,     // (A,O,T)
    float*       __restrict__ out)              // (3,A,M)
{
    extern __shared__ float4 s_o4[];            // [slot][t]
    float* s_px = (float*)(s_o4 + NO * NT);     // [NM][NT]
    float* s_py = s_px + NM * NT;

    __shared__ float s_tm[NT], s_hwi[NT], s_tgx[NT], s_tgy[NT];
    __shared__ int   s_cnt[NT];
    __shared__ int   ccnt[NM];

    const int a   = blockIdx.x;
    const int tid = threadIdx.x;

    if (tid < NM) ccnt[tid] = 0;
    if (tid < NT) s_cnt[tid] = 0;

    // Per-timestep ego data: mask, half-width (invalid -> -1), masked target.
    if (tid < NT) {
        int t = tid;
        float tm = (float)target_mask[a * NT + t];
        s_tm[t]  = tm;
        s_hwi[t] = (tm > 0.0f) ? 0.5f * agent_fut_width[a * NT + t] : -1.0f;
        float2 tg = ((const float2*)targets)[a * NT + t];
        s_tgx[t] = __fmul_rn(tm, tg.x);
        s_tgy[t] = __fmul_rn(tm, tg.y);
    }
    __syncthreads();   // s_tm ready; s_cnt zeroed

    // ---- Streaming phase: unconditional vectorized loads, max MLP ----

    // Masked predictions (xy of the 4-vector), [m][t]. 1280 float4 over 1024 thr.
    {
        const float4* pb = (const float4*)traj_preds + a * NM * NT;
        int i = tid;
        float4 p = pb[i];
        float tm = s_tm[i % NT];
        s_px[i] = __fmul_rn(tm, p.x);
        s_py[i] = __fmul_rn(tm, p.y);
        if (tid < NM * NT - BLK) {              // 256 threads take a 2nd task
            int i2 = tid + BLK;
            float4 p2 = pb[i2];
            float tm2 = s_tm[i2 % NT];
            s_px[i2] = __fmul_rn(tm2, p2.x);
            s_py[i2] = __fmul_rn(tm2, p2.y);
        }
    }

    // Compact valid others per timestep into [slot][t] float4 layout.
    // Vector tasks of 4 consecutive t (NT%4==0 -> same o). 1280 tasks.
    {
        const int base = a * NO * NT;
        const int4*   mkp = (const int4*)  (other_masks  + base);
        const float4* wdp = (const float4*)(other_widths + base);
        const float4* trp = (const float4*)(other_trajs  + 2 * base);
        const int NV = NO * NT / 4;             // 1280
        #pragma unroll 1
        for (int v = tid; v < NV; v += BLK) {
            int4   mk  = mkp[v];
            float4 wd  = wdp[v];
            float4 xy0 = trp[2 * v];            // (x0,y0,x1,y1)
            float4 xy1 = trp[2 * v + 1];        // (x2,y2,x3,y3)
            int t0 = (4 * v) % NT;
            if (mk.x > 0) { int s = atomicAdd(&s_cnt[t0+0], 1);
                s_o4[s * NT + t0 + 0] = make_float4(xy0.x, xy0.y, 0.5f * wd.x, 0.0f); }
            if (mk.y > 0) { int s = atomicAdd(&s_cnt[t0+1], 1);
                s_o4[s * NT + t0 + 1] = make_float4(xy0.z, xy0.w, 0.5f * wd.y, 0.0f); }
            if (mk.z > 0) { int s = atomicAdd(&s_cnt[t0+2], 1);
                s_o4[s * NT + t0 + 2] = make_float4(xy1.x, xy1.y, 0.5f * wd.z, 0.0f); }
            if (mk.w > 0) { int s = atomicAdd(&s_cnt[t0+3], 1);
                s_o4[s * NT + t0 + 3] = make_float4(xy1.z, xy1.w, 0.5f * wd.w, 0.0f); }
        }
    }
    __syncthreads();

    // L2 path: warp w (<16) handles mode w; fixed-order shuffle tree.
    {
        int wid = tid >> 5, lane = tid & 31;
        if (wid < NM) {
            const float* px = s_px + wid * NT;
            const float* py = s_py + wid * NT;
            float acc = 0.0f;
            #pragma unroll
            for (int k = 0; k < 3; k++) {
                int t = lane + k * 32;
                if (t < NT) {
                    float dx = __fsub_rn(px[t], s_tgx[t]);
                    float dy = __fsub_rn(py[t], s_tgy[t]);
                    float s  = __fadd_rn(__fmul_rn(dx, dx), __fmul_rn(dy, dy));
                    if (s > 0.0f) acc = __fadd_rn(acc, __fsqrt_rn(s));
                }
            }
            #pragma unroll
            for (int off = 16; off > 0; off >>= 1)
                acc = __fadd_rn(acc, __shfl_xor_sync(0xffffffffu, acc, off));
            if (lane == 0)
                out[2 * NA * NM + a * NM + wid] = __fsub_rn(8.0f, acc);  // l2_penalty
        }
    }

    // Collision path: task = (m,t); ANY compacted other within radius?
    #pragma unroll 1
    for (int p = tid; p < NM * NT; p += BLK) {
        int m = p / NT;
        int t = p - m * NT;
        float hwi = s_hwi[t];
        if (hwi < 0.0f) continue;                 // ego invalid at t
        float px = s_px[m * NT + t];
        float py = s_py[m * NT + t];
        const float4* bp = s_o4 + t;
        int n = s_cnt[t];
        int hit = 0;
        int o = 0;
        #pragma unroll 1
        for (; o + 4 <= n; o += 4) {
            float4 c0 = bp[(o + 0) * NT];
            float4 c1 = bp[(o + 1) * NT];
            float4 c2 = bp[(o + 2) * NT];
            float4 c3 = bp[(o + 3) * NT];
            float dx0 = __fsub_rn(px, c0.x), dy0 = __fsub_rn(py, c0.y);
            float dx1 = __fsub_rn(px, c1.x), dy1 = __fsub_rn(py, c1.y);
            float dx2 = __fsub_rn(px, c2.x), dy2 = __fsub_rn(py, c2.y);
            float dx3 = __fsub_rn(px, c3.x), dy3 = __fsub_rn(py, c3.y);
            float d20 = __fadd_rn(__fmul_rn(dx0, dx0), __fmul_rn(dy0, dy0));
            float d21 = __fadd_rn(__fmul_rn(dx1, dx1), __fmul_rn(dy1, dy1));
            float d22 = __fadd_rn(__fmul_rn(dx2, dx2), __fmul_rn(dy2, dy2));
            float d23 = __fadd_rn(__fmul_rn(dx3, dx3), __fmul_rn(dy3, dy3));
            float r0 = __fadd_rn(hwi, c0.z), r1 = __fadd_rn(hwi, c1.z);
            float r2 = __fadd_rn(hwi, c2.z), r3 = __fadd_rn(hwi, c3.z);
            // conservative squared filter (r <= 2, no overflow)
            bool f0 = d20 <= __fmul_rn(r0, r0) * 1.00001f;
            bool f1 = d21 <= __fmul_rn(r1, r1) * 1.00001f;
            bool f2 = d22 <= __fmul_rn(r2, r2) * 1.00001f;
            bool f3 = d23 <= __fmul_rn(r3, r3) * 1.00001f;
            if (f0 | f1 | f2 | f3) {              // rare: exact correctly-rounded test
                if ((__fsqrt_rn(d20) <= r0) | (__fsqrt_rn(d21) <= r1) |
                    (__fsqrt_rn(d22) <= r2) | (__fsqrt_rn(d23) <= r3)) { hit = 1; break; }
            }
        }
        if (!hit) {
            for (; o < n; o++) {
                float4 c = bp[o * NT];
                float dx = __fsub_rn(px, c.x), dy = __fsub_rn(py, c.y);
                float d2 = __fadd_rn(__fmul_rn(dx, dx), __fmul_rn(dy, dy));
                float r  = __fadd_rn(hwi, c.z);
                if (d2 <= __fmul_rn(r, r) * 1.00001f) {
                    if (__fsqrt_rn(d2) <= r) { hit = 1; break; }
                }
            }
        }
        if (hit) atomicAdd(&ccnt[m], 1);          // integer -> deterministic
    }
    __syncthreads();

    if (tid < NM) {
        int idx = a * NM + tid;
        float l2p = out[2 * NA * NM + idx];
        float cp  = __fmul_rn(-100.0f, (float)ccnt[tid]);
        out[idx]           = __fadd_rn(l2p, cp);   // total
        out[NA * NM + idx] = cp;                   // collision_penalty
    }
}

extern "C" void kernel_launch(void* const* d_in, const int* in_sizes, int n_in,
                              void* d_out, int out_size) {
    const float* targets         = (const float*)d_in[0];
    const int*   target_mask     = (const int*)  d_in[1];
    const float* traj_preds      = (const float*)d_in[2];
    // d_in[3] = mode_probs (unused by reference)
    const float* agent_fut_width = (const float*)d_in[4];
    const float* other_trajs     = (const float*)d_in[5];
    const int*   other_masks     = (const int*)  d_in[6];
    const float* other_widths    = (const float*)d_in[7];
    float* out = (float*)d_out;

    cudaFuncSetAttribute(path_reward_collision_kernel,
                         cudaFuncAttributeMaxDynamicSharedMemorySize, SMEM_BYTES);
    path_reward_collision_kernel<<<NA, BLK, SMEM_BYTES>>>(
        targets, target_mask, traj_preds, agent_fut_width,
        other_trajs, other_masks, other_widths, out);
}

// round 5
// speedup vs baseline: 1.7035x; 1.0077x over previous
#include <cuda_runtime.h>

#define NA 256
#define NM 16
#define NT 80
#define NO 64
#define BLK 1024

// Dynamic smem:
//   s_o4 [NO*NT] float4  compacted valid others (x, y, r, r^2*1.00001), [slot][t]
//   s_px [NM*NT], s_py [NM*NT]  masked ego preds
static const int SMEM_BYTES = NO * NT * 16 + 2 * NM * NT * 4;   // 92160

__global__ __launch_bounds__(BLK, 2) void path_reward_collision_kernel(
    const float* __restrict__ targets,          // (A,T,2)
    const int*   __restrict__ target_mask,      // (A,T)
    const float* __restrict__ traj_preds,       // (A,M,T,4)
    const float* __restrict__ agent_fut_width,  // (A,T)
    const float* __restrict__ other_trajs,      // (A,O,T,2)
    const int*   __restrict__ other_masks,      // (A,O,T)
    const float* __restrict__ other_widths,     // (A,O,T)
    float*       __restrict__ out)              // (3,A,M)
{
    extern __shared__ float4 s_o4[];            // [slot][t]
    float* s_px = (float*)(s_o4 + NO * NT);     // [NM][NT]
    float* s_py = s_px + NM * NT;

    __shared__ float s_tm[NT], s_hwi[NT], s_tgx[NT], s_tgy[NT];
    __shared__ int   s_cnt[NT];
    __shared__ int   s_vt[NT];                  // sorted list of ego-valid timesteps
    __shared__ int   s_nvt;
    __shared__ int   ccnt[NM];

    const int a   = blockIdx.x;
    const int tid = threadIdx.x;

    if (tid < NM) ccnt[tid] = 0;
    if (tid < NT) s_cnt[tid] = 0;

    // Per-timestep ego data: mask, half-width (invalid -> -1), masked target.
    if (tid < NT) {
        int t = tid;
        float tm = (float)target_mask[a * NT + t];
        s_tm[t]  = tm;
        s_hwi[t] = (tm > 0.0f) ? 0.5f * agent_fut_width[a * NT + t] : -1.0f;
        float2 tg = ((const float2*)targets)[a * NT + t];
        s_tgx[t] = __fmul_rn(tm, tg.x);
        s_tgy[t] = __fmul_rn(tm, tg.y);
    }
    __syncthreads();   // s_tm, s_hwi ready; s_cnt zeroed

    // Warp 0: build sorted valid-timestep list via ballot scan.
    if (tid < 32) {
        int lane = tid;
        int base = 0;
        #pragma unroll
        for (int k = 0; k < 3; k++) {
            int t = k * 32 + lane;
            bool v = (t < NT) && (s_hwi[t] >= 0.0f);
            unsigned mask = __ballot_sync(0xffffffffu, v);
            if (v) s_vt[base + __popc(mask & ((1u << lane) - 1u))] = t;
            base += __popc(mask);
        }
        if (lane == 0) s_nvt = base;
    }

    // Masked predictions (xy of the 4-vector), [m][t]. 1280 float4 over 1024 thr.
    {
        const float4* pb = (const float4*)traj_preds + a * NM * NT;
        int i = tid;
        float4 p = pb[i];
        float tm = s_tm[i % NT];
        s_px[i] = __fmul_rn(tm, p.x);
        s_py[i] = __fmul_rn(tm, p.y);
        if (tid < NM * NT - BLK) {              // 256 threads take a 2nd task
            int i2 = tid + BLK;
            float4 p2 = pb[i2];
            float tm2 = s_tm[i2 % NT];
            s_px[i2] = __fmul_rn(tm2, p2.x);
            s_py[i2] = __fmul_rn(tm2, p2.y);
        }
    }

    // Compact valid others per timestep into [slot][t] float4, folding the
    // radius: r = hwi(t) + 0.5*w_o (bit-identical to reference ordering),
    // plus the conservative squared filter bound r^2 * 1.00001.
    {
        const int base = a * NO * NT;
        const int4*   mkp = (const int4*)  (other_masks  + base);
        const float4* wdp = (const float4*)(other_widths + base);
        const float4* trp = (const float4*)(other_trajs  + 2 * base);
        const int NV = NO * NT / 4;             // 1280
        #pragma unroll 1
        for (int v = tid; v < NV; v += BLK) {
            int4   mk  = mkp[v];
            float4 wd  = wdp[v];
            float4 xy0 = trp[2 * v];            // (x0,y0,x1,y1)
            float4 xy1 = trp[2 * v + 1];        // (x2,y2,x3,y3)
            int t0 = (4 * v) % NT;
            if (mk.x > 0) { int s = atomicAdd(&s_cnt[t0+0], 1);
                float r = __fadd_rn(s_hwi[t0+0], 0.5f * wd.x);
                s_o4[s * NT + t0 + 0] = make_float4(xy0.x, xy0.y, r, __fmul_rn(r, r) * 1.00001f); }
            if (mk.y > 0) { int s = atomicAdd(&s_cnt[t0+1], 1);
                float r = __fadd_rn(s_hwi[t0+1], 0.5f * wd.y);
                s_o4[s * NT + t0 + 1] = make_float4(xy0.z, xy0.w, r, __fmul_rn(r, r) * 1.00001f); }
            if (mk.z > 0) { int s = atomicAdd(&s_cnt[t0+2], 1);
                float r = __fadd_rn(s_hwi[t0+2], 0.5f * wd.z);
                s_o4[s * NT + t0 + 2] = make_float4(xy1.x, xy1.y, r, __fmul_rn(r, r) * 1.00001f); }
            if (mk.w > 0) { int s = atomicAdd(&s_cnt[t0+3], 1);
                float r = __fadd_rn(s_hwi[t0+3], 0.5f * wd.w);
                s_o4[s * NT + t0 + 3] = make_float4(xy1.z, xy1.w, r, __fmul_rn(r, r) * 1.00001f); }
        }
    }
    __syncthreads();

    // L2 path: warp w (<16) handles mode w; fixed-order shuffle tree.
    {
        int wid = tid >> 5, lane = tid & 31;
        if (wid < NM) {
            const float* px = s_px + wid * NT;
            const float* py = s_py + wid * NT;
            float acc = 0.0f;
            #pragma unroll
            for (int k = 0; k < 3; k++) {
                int t = lane + k * 32;
                if (t < NT) {
                    float dx = __fsub_rn(px[t], s_tgx[t]);
                    float dy = __fsub_rn(py[t], s_tgy[t]);
                    float s  = __fadd_rn(__fmul_rn(dx, dx), __fmul_rn(dy, dy));
                    if (s > 0.0f) acc = __fadd_rn(acc, __fsqrt_rn(s));
                }
            }
            #pragma unroll
            for (int off = 16; off > 0; off >>= 1)
                acc = __fadd_rn(acc, __shfl_xor_sync(0xffffffffu, acc, off));
            if (lane == 0)
                out[2 * NA * NM + a * NM + wid] = __fsub_rn(8.0f, acc);  // l2_penalty
        }
    }

    // Collision path: tasks = (m, valid-t) only -> all lanes do real work.
    {
        const int nvt = s_nvt;
        const int ntask = NM * nvt;
        #pragma unroll 1
        for (int p = tid; p < ntask; p += BLK) {
            int m = p / nvt;
            int t = s_vt[p - m * nvt];
            float px = s_px[m * NT + t];
            float py = s_py[m * NT + t];
            const float4* bp = s_o4 + t;
            int n = s_cnt[t];
            int hit = 0;
            int o = 0;
            #pragma unroll 1
            for (; o + 4 <= n; o += 4) {
                float4 c0 = bp[(o + 0) * NT];
                float4 c1 = bp[(o + 1) * NT];
                float4 c2 = bp[(o + 2) * NT];
                float4 c3 = bp[(o + 3) * NT];
                float dx0 = __fsub_rn(px, c0.x), dy0 = __fsub_rn(py, c0.y);
                float dx1 = __fsub_rn(px, c1.x), dy1 = __fsub_rn(py, c1.y);
                float dx2 = __fsub_rn(px, c2.x), dy2 = __fsub_rn(py, c2.y);
                float dx3 = __fsub_rn(px, c3.x), dy3 = __fsub_rn(py, c3.y);
                float d20 = __fadd_rn(__fmul_rn(dx0, dx0), __fmul_rn(dy0, dy0));
                float d21 = __fadd_rn(__fmul_rn(dx1, dx1), __fmul_rn(dy1, dy1));
                float d22 = __fadd_rn(__fmul_rn(dx2, dx2), __fmul_rn(dy2, dy2));
                float d23 = __fadd_rn(__fmul_rn(dx3, dx3), __fmul_rn(dy3, dy3));
                // conservative squared filter (bound precomputed at compaction)
                bool f0 = d20 <= c0.w;
                bool f1 = d21 <= c1.w;
                bool f2 = d22 <= c2.w;
                bool f3 = d23 <= c3.w;
                if (f0 | f1 | f2 | f3) {          // rare: exact correctly-rounded test
                    if ((__fsqrt_rn(d20) <= c0.z) | (__fsqrt_rn(d21) <= c1.z) |
                        (__fsqrt_rn(d22) <= c2.z) | (__fsqrt_rn(d23) <= c3.z)) { hit = 1; break; }
                }
            }
            if (!hit) {
                for (; o < n; o++) {
                    float4 c = bp[o * NT];
                    float dx = __fsub_rn(px, c.x), dy = __fsub_rn(py, c.y);
                    float d2 = __fadd_rn(__fmul_rn(dx, dx), __fmul_rn(dy, dy));
                    if (d2 <= c.w) {
                        if (__fsqrt_rn(d2) <= c.z) { hit = 1; break; }
                    }
                }
            }
            if (hit) atomicAdd(&ccnt[m], 1);      // integer -> deterministic
        }
    }
    __syncthreads();

    if (tid < NM) {
        int idx = a * NM + tid;
        float l2p = out[2 * NA * NM + idx];
        float cp  = __fmul_rn(-100.0f, (float)ccnt[tid]);
        out[idx]           = __fadd_rn(l2p, cp);   // total
        out[NA * NM + idx] = cp;                   // collision_penalty
    }
}

extern "C" void kernel_launch(void* const* d_in, const int* in_sizes, int n_in,
                              void* d_out, int out_size) {
    const float* targets         = (const float*)d_in[0];
    const int*   target_mask     = (const int*)  d_in[1];
    const float* traj_preds      = (const float*)d_in[2];
    // d_in[3] = mode_probs (unused by reference)
    const float* agent_fut_width = (const float*)d_in[4];
    const float* other_trajs     = (const float*)d_in[5];
    const int*   other_masks     = (const int*)  d_in[6];
    const float* other_widths    = (const float*)d_in[7];
    float* out = (float*)d_out;

    cudaFuncSetAttribute(path_reward_collision_kernel,
                         cudaFuncAttributeMaxDynamicSharedMemorySize, SMEM_BYTES);
    path_reward_collision_kernel<<<NA, BLK, SMEM_BYTES>>>(
        targets, target_mask, traj_preds, agent_fut_width,
        other_trajs, other_masks, other_widths, out);
}

// round 10
// speedup vs baseline: 1.8453x; 1.0832x over previous
#include <cuda_runtime.h>

#define NA 256
#define NM 16
#define NT 80
#define NO 64
#define OP 65            // padded per-t slot stride (65*4 words ≡ 4 mod 32 per lane -> conflict-free reads)
#define BLK 1024

// Dynamic smem:
//   s_o4 [NT*OP] float4  all candidates (x, y, r, r^2*1.00001 | -1 if invalid), [t][o]
//   s_px [NM*NT], s_py [NM*NT]  masked ego preds
static const int SMEM_BYTES = NT * OP * 16 + 2 * NM * NT * 4;   // 83200 + 10240 = 93440

__global__ __launch_bounds__(BLK, 2) void path_reward_collision_kernel(
    const float* __restrict__ targets,          // (A,T,2)
    const int*   __restrict__ target_mask,      // (A,T)
    const float* __restrict__ traj_preds,       // (A,M,T,4)
    const float* __restrict__ agent_fut_width,  // (A,T)
    const float* __restrict__ other_trajs,      // (A,O,T,2)
    const int*   __restrict__ other_masks,      // (A,O,T)
    const float* __restrict__ other_widths,     // (A,O,T)
    float*       __restrict__ out)              // (3,A,M)
{
    extern __shared__ float4 s_o4[];            // [t][o] padded
    float* s_px = (float*)(s_o4 + NT * OP);     // [NM][NT]
    float* s_py = s_px + NM * NT;

    __shared__ float    s_tm[NT], s_hwi[NT], s_tgx[NT], s_tgy[NT];
    __shared__ int      s_vt[NT];               // sorted list of ego-valid timesteps
    __shared__ int      s_nvt;
    __shared__ unsigned s_hit[NT];              // per-t bitmask of colliding modes
    __shared__ float    s_l2[NM];

    const int a   = blockIdx.x;
    const int tid = threadIdx.x;

    // Per-timestep ego data: mask, half-width (invalid -> -1), masked target.
    if (tid < NT) {
        int t = tid;
        float tm = (float)target_mask[a * NT + t];
        s_tm[t]  = tm;
        s_hwi[t] = (tm > 0.0f) ? 0.5f * agent_fut_width[a * NT + t] : -1.0f;
        float2 tg = ((const float2*)targets)[a * NT + t];
        s_tgx[t] = __fmul_rn(tm, tg.x);
        s_tgy[t] = __fmul_rn(tm, tg.y);
    }
    __syncthreads();   // s_tm, s_hwi ready

    // Warp 0: sorted valid-timestep list via ballot scan.
    if (tid < 32) {
        int lane = tid;
        int base = 0;
        #pragma unroll
        for (int k = 0; k < 3; k++) {
            int t = k * 32 + lane;
            bool v = (t < NT) && (s_hwi[t] >= 0.0f);
            unsigned mask = __ballot_sync(0xffffffffu, v);
            if (v) s_vt[base + __popc(mask & ((1u << lane) - 1u))] = t;
            base += __popc(mask);
        }
        if (lane == 0) s_nvt = base;
    }

    // Masked predictions (xy of the 4-vector), [m][t]. 1280 float4 over 1024 thr.
    {
        const float4* pb = (const float4*)traj_preds + a * NM * NT;
        int i = tid;
        float4 p = pb[i];
        float tm = s_tm[i % NT];
        s_px[i] = __fmul_rn(tm, p.x);
        s_py[i] = __fmul_rn(tm, p.y);
        if (tid < NM * NT - BLK) {              // 256 threads take a 2nd task
            int i2 = tid + BLK;
            float4 p2 = pb[i2];
            float tm2 = s_tm[i2 % NT];
            s_px[i2] = __fmul_rn(tm2, p2.x);
            s_py[i2] = __fmul_rn(tm2, p2.y);
        }
    }

    // All candidates to fixed slots [t][o]; fold radius r = hwi(t)+0.5*w_o and
    // the conservative filter bound r^2*1.00001. Invalid -> bound -1 (never passes).
    {
        const int base = a * NO * NT;
        const int4*   mkp = (const int4*)  (other_masks  + base);
        const float4* wdp = (const float4*)(other_widths + base);
        const float4* trp = (const float4*)(other_trajs  + 2 * base);
        const int NV = NO * NT / 4;             // 1280
        #pragma unroll 1
        for (int v = tid; v < NV; v += BLK) {
            int4   mk  = mkp[v];
            float4 wd  = wdp[v];
            float4 xy0 = trp[2 * v];            // (x0,y0,x1,y1)
            float4 xy1 = trp[2 * v + 1];        // (x2,y2,x3,y3)
            int o  = v / (NT / 4);
            int t0 = 4 * (v % (NT / 4));
            float4 c;
            if (mk.x > 0) { float r = __fadd_rn(s_hwi[t0+0], 0.5f * wd.x);
                c = make_float4(xy0.x, xy0.y, r, __fmul_rn(r, r) * 1.00001f); }
            else c = make_float4(0.f, 0.f, -1.f, -1.f);
            s_o4[(t0 + 0) * OP + o] = c;
            if (mk.y > 0) { float r = __fadd_rn(s_hwi[t0+1], 0.5f * wd.y);
                c = make_float4(xy0.z, xy0.w, r, __fmul_rn(r, r) * 1.00001f); }
            else c = make_float4(0.f, 0.f, -1.f, -1.f);
            s_o4[(t0 + 1) * OP + o] = c;
            if (mk.z > 0) { float r = __fadd_rn(s_hwi[t0+2], 0.5f * wd.z);
                c = make_float4(xy1.x, xy1.y, r, __fmul_rn(r, r) * 1.00001f); }
            else c = make_float4(0.f, 0.f, -1.f, -1.f);
            s_o4[(t0 + 2) * OP + o] = c;
            if (mk.w > 0) { float r = __fadd_rn(s_hwi[t0+3], 0.5f * wd.w);
                c = make_float4(xy1.z, xy1.w, r, __fmul_rn(r, r) * 1.00001f); }
            else c = make_float4(0.f, 0.f, -1.f, -1.f);
            s_o4[(t0 + 3) * OP + o] = c;
        }
    }
    __syncthreads();

    // L2 path: warp w (<16) handles mode w; fixed-order shuffle tree.
    {
        int wid = tid >> 5, lane = tid & 31;
        if (wid < NM) {
            const float* px = s_px + wid * NT;
            const float* py = s_py + wid * NT;
            float acc = 0.0f;
            #pragma unroll
            for (int k = 0; k < 3; k++) {
                int t = lane + k * 32;
                if (t < NT) {
                    float dx = __fsub_rn(px[t], s_tgx[t]);
                    float dy = __fsub_rn(py[t], s_tgy[t]);
                    float s  = __fadd_rn(__fmul_rn(dx, dx), __fmul_rn(dy, dy));
                    if (s > 0.0f) acc = __fadd_rn(acc, __fsqrt_rn(s));
                }
            }
            #pragma unroll
            for (int off = 16; off > 0; off >>= 1)
                acc = __fadd_rn(acc, __shfl_xor_sync(0xffffffffu, acc, off));
            if (lane == 0) s_l2[wid] = __fsub_rn(8.0f, acc);   // l2_penalty
        }
    }

    // Collision phase: one warp per valid t. lane = candidate slot (2 per lane).
    // Each candidate is loaded ONCE; all 16 modes tested via broadcast px/py.
    {
        const int nvt  = s_nvt;
        const int wid  = tid >> 5, lane = tid & 31;
        #pragma unroll 1
        for (int v = wid; v < nvt; v += BLK / 32) {
            int t = s_vt[v];
            unsigned mask = 0;
            #pragma unroll
            for (int p = 0; p < 2; p++) {
                float4 c = s_o4[t * OP + lane + 32 * p];
                #pragma unroll
                for (int m = 0; m < NM; m++) {
                    float dx = __fsub_rn(s_px[m * NT + t], c.x);
                    float dy = __fsub_rn(s_py[m * NT + t], c.y);
                    float d2 = __fadd_rn(__fmul_rn(dx, dx), __fmul_rn(dy, dy));
                    if (d2 <= c.w) {                       // conservative filter (rare)
                        if (__fsqrt_rn(d2) <= c.z) mask |= 1u << m;  // exact test
                    }
                }
            }
            mask = __reduce_or_sync(0xffffffffu, mask);
            if (lane == 0) s_hit[t] = mask;
        }
    }
    __syncthreads();

    // Outputs: thread m counts timesteps whose hit-word has bit m set.
    if (tid < NM) {
        int nvt = s_nvt;
        int cnt = 0;
        for (int v = 0; v < nvt; v++)
            cnt += (int)((s_hit[s_vt[v]] >> tid) & 1u);
        int idx = a * NM + tid;
        float l2p = s_l2[tid];
        float cp  = __fmul_rn(-100.0f, (float)cnt);
        out[idx]               = __fadd_rn(l2p, cp);   // total
        out[NA * NM + idx]     = cp;                   // collision_penalty
        out[2 * NA * NM + idx] = l2p;                  // l2_penalty
    }
}

extern "C" void kernel_launch(void* const* d_in, const int* in_sizes, int n_in,
                              void* d_out, int out_size) {
    const float* targets         = (const float*)d_in[0];
    const int*   target_mask     = (const int*)  d_in[1];
    const float* traj_preds      = (const float*)d_in[2];
    // d_in[3] = mode_probs (unused by reference)
    const float* agent_fut_width = (const float*)d_in[4];
    const float* other_trajs     = (const float*)d_in[5];
    const int*   other_masks     = (const int*)  d_in[6];
    const float* other_widths    = (const float*)d_in[7];
    float* out = (float*)d_out;

    cudaFuncSetAttribute(path_reward_collision_kernel,
                         cudaFuncAttributeMaxDynamicSharedMemorySize, SMEM_BYTES);
    path_reward_collision_kernel<<<NA, BLK, SMEM_BYTES>>>(
        targets, target_mask, traj_preds, agent_fut_width,
        other_trajs, other_masks, other_widths, out);
}

// round 11
// speedup vs baseline: 1.8483x; 1.0017x over previous
#include <cuda_runtime.h>

#define NA 256
#define NM 16
#define NT 80
#define NO 64
#define OP 65            // padded per-t slot stride (65*4 words ≡ 4 mod 32 per lane -> conflict-free reads)
#define BLK 1024

// Dynamic smem:
//   s_o4 [NT*OP] float4  all candidates (x, y, r, r^2*1.00001 | -1 if invalid), [t][o]
//   s_px [NM*NT], s_py [NM*NT]  masked ego preds
static const int SMEM_BYTES = NT * OP * 16 + 2 * NM * NT * 4;   // 83200 + 10240 = 93440

__global__ __launch_bounds__(BLK, 2) void path_reward_collision_kernel(
    const float* __restrict__ targets,          // (A,T,2)
    const int*   __restrict__ target_mask,      // (A,T)
    const float* __restrict__ traj_preds,       // (A,M,T,4)
    const float* __restrict__ agent_fut_width,  // (A,T)
    const float* __restrict__ other_trajs,      // (A,O,T,2)
    const int*   __restrict__ other_masks,      // (A,O,T)
    const float* __restrict__ other_widths,     // (A,O,T)
    float*       __restrict__ out)              // (3,A,M)
{
    extern __shared__ float4 s_o4[];            // [t][o] padded
    float* s_px = (float*)(s_o4 + NT * OP);     // [NM][NT]
    float* s_py = s_px + NM * NT;

    __shared__ float    s_tm[NT], s_hwi[NT], s_tgx[NT], s_tgy[NT];
    __shared__ int      s_vt[NT];               // sorted list of ego-valid timesteps
    __shared__ int      s_nvt;
    __shared__ unsigned s_hit[NT];              // per-t bitmask of colliding modes
    __shared__ float    s_l2[NM];

    const int a   = blockIdx.x;
    const int tid = threadIdx.x;

    // Per-timestep ego data: mask, half-width (invalid -> -1), masked target.
    if (tid < NT) {
        int t = tid;
        float tm = (float)target_mask[a * NT + t];
        s_tm[t]  = tm;
        s_hwi[t] = (tm > 0.0f) ? 0.5f * agent_fut_width[a * NT + t] : -1.0f;
        float2 tg = ((const float2*)targets)[a * NT + t];
        s_tgx[t] = __fmul_rn(tm, tg.x);
        s_tgy[t] = __fmul_rn(tm, tg.y);
    }
    __syncthreads();   // s_tm, s_hwi ready

    // Warp 0: sorted valid-timestep list via ballot scan.
    if (tid < 32) {
        int lane = tid;
        int base = 0;
        #pragma unroll
        for (int k = 0; k < 3; k++) {
            int t = k * 32 + lane;
            bool v = (t < NT) && (s_hwi[t] >= 0.0f);
            unsigned mask = __ballot_sync(0xffffffffu, v);
            if (v) s_vt[base + __popc(mask & ((1u << lane) - 1u))] = t;
            base += __popc(mask);
        }
        if (lane == 0) s_nvt = base;
    }

    // Masked predictions (xy of the 4-vector), [m][t]. 1280 float4 over 1024 thr.
    {
        const float4* pb = (const float4*)traj_preds + a * NM * NT;
        int i = tid;
        float4 p = pb[i];
        float tm = s_tm[i % NT];
        s_px[i] = __fmul_rn(tm, p.x);
        s_py[i] = __fmul_rn(tm, p.y);
        if (tid < NM * NT - BLK) {              // 256 threads take a 2nd task
            int i2 = tid + BLK;
            float4 p2 = pb[i2];
            float tm2 = s_tm[i2 % NT];
            s_px[i2] = __fmul_rn(tm2, p2.x);
            s_py[i2] = __fmul_rn(tm2, p2.y);
        }
    }

    // All candidates to fixed slots [t][o]; fold radius r = hwi(t)+0.5*w_o and
    // the conservative filter bound r^2*1.00001. Invalid -> bound -1 (never passes).
    {
        const int base = a * NO * NT;
        const int4*   mkp = (const int4*)  (other_masks  + base);
        const float4* wdp = (const float4*)(other_widths + base);
        const float4* trp = (const float4*)(other_trajs  + 2 * base);
        const int NV = NO * NT / 4;             // 1280
        #pragma unroll 1
        for (int v = tid; v < NV; v += BLK) {
            int4   mk  = mkp[v];
            float4 wd  = wdp[v];
            float4 xy0 = trp[2 * v];            // (x0,y0,x1,y1)
            float4 xy1 = trp[2 * v + 1];        // (x2,y2,x3,y3)
            int o  = v / (NT / 4);
            int t0 = 4 * (v % (NT / 4));
            float4 c;
            if (mk.x > 0) { float r = __fadd_rn(s_hwi[t0+0], 0.5f * wd.x);
                c = make_float4(xy0.x, xy0.y, r, __fmul_rn(r, r) * 1.00001f); }
            else c = make_float4(0.f, 0.f, -1.f, -1.f);
            s_o4[(t0 + 0) * OP + o] = c;
            if (mk.y > 0) { float r = __fadd_rn(s_hwi[t0+1], 0.5f * wd.y);
                c = make_float4(xy0.z, xy0.w, r, __fmul_rn(r, r) * 1.00001f); }
            else c = make_float4(0.f, 0.f, -1.f, -1.f);
            s_o4[(t0 + 1) * OP + o] = c;
            if (mk.z > 0) { float r = __fadd_rn(s_hwi[t0+2], 0.5f * wd.z);
                c = make_float4(xy1.x, xy1.y, r, __fmul_rn(r, r) * 1.00001f); }
            else c = make_float4(0.f, 0.f, -1.f, -1.f);
            s_o4[(t0 + 2) * OP + o] = c;
            if (mk.w > 0) { float r = __fadd_rn(s_hwi[t0+3], 0.5f * wd.w);
                c = make_float4(xy1.z, xy1.w, r, __fmul_rn(r, r) * 1.00001f); }
            else c = make_float4(0.f, 0.f, -1.f, -1.f);
            s_o4[(t0 + 3) * OP + o] = c;
        }
    }
    __syncthreads();

    // L2 path: warp w (<16) handles mode w; fixed-order shuffle tree.
    {
        int wid = tid >> 5, lane = tid & 31;
        if (wid < NM) {
            const float* px = s_px + wid * NT;
            const float* py = s_py + wid * NT;
            float acc = 0.0f;
            #pragma unroll
            for (int k = 0; k < 3; k++) {
                int t = lane + k * 32;
                if (t < NT) {
                    float dx = __fsub_rn(px[t], s_tgx[t]);
                    float dy = __fsub_rn(py[t], s_tgy[t]);
                    float s  = __fadd_rn(__fmul_rn(dx, dx), __fmul_rn(dy, dy));
                    if (s > 0.0f) acc = __fadd_rn(acc, __fsqrt_rn(s));
                }
            }
            #pragma unroll
            for (int off = 16; off > 0; off >>= 1)
                acc = __fadd_rn(acc, __shfl_xor_sync(0xffffffffu, acc, off));
            if (lane == 0) s_l2[wid] = __fsub_rn(8.0f, acc);   // l2_penalty
        }
    }

    // Collision phase: one warp per valid t. lane = candidate slot (2 per lane).
    // Each candidate is loaded ONCE; all 16 modes tested via broadcast px/py.
    {
        const int nvt  = s_nvt;
        const int wid  = tid >> 5, lane = tid & 31;
        #pragma unroll 1
        for (int v = wid; v < nvt; v += BLK / 32) {
            int t = s_vt[v];
            unsigned mask = 0;
            #pragma unroll
            for (int p = 0; p < 2; p++) {
                float4 c = s_o4[t * OP + lane + 32 * p];
                #pragma unroll
                for (int m = 0; m < NM; m++) {
                    float dx = __fsub_rn(s_px[m * NT + t], c.x);
                    float dy = __fsub_rn(s_py[m * NT + t], c.y);
                    float d2 = __fadd_rn(__fmul_rn(dx, dx), __fmul_rn(dy, dy));
                    if (d2 <= c.w) {                       // conservative filter (rare)
                        if (__fsqrt_rn(d2) <= c.z) mask |= 1u << m;  // exact test
                    }
                }
            }
            mask = __reduce_or_sync(0xffffffffu, mask);
            if (lane == 0) s_hit[t] = mask;
        }
    }
    __syncthreads();

    // Outputs: thread m counts timesteps whose hit-word has bit m set.
    if (tid < NM) {
        int nvt = s_nvt;
        int cnt = 0;
        for (int v = 0; v < nvt; v++)
            cnt += (int)((s_hit[s_vt[v]] >> tid) & 1u);
        int idx = a * NM + tid;
        float l2p = s_l2[tid];
        float cp  = __fmul_rn(-100.0f, (float)cnt);
        out[idx]               = __fadd_rn(l2p, cp);   // total
        out[NA * NM + idx]     = cp;                   // collision_penalty
        out[2 * NA * NM + idx] = l2p;                  // l2_penalty
    }
}

extern "C" void kernel_launch(void* const* d_in, const int* in_sizes, int n_in,
                              void* d_out, int out_size) {
    const float* targets         = (const float*)d_in[0];
    const int*   target_mask     = (const int*)  d_in[1];
    const float* traj_preds      = (const float*)d_in[2];
    // d_in[3] = mode_probs (unused by reference)
    const float* agent_fut_width = (const float*)d_in[4];
    const float* other_trajs     = (const float*)d_in[5];
    const int*   other_masks     = (const int*)  d_in[6];
    const float* other_widths    = (const float*)d_in[7];
    float* out = (float*)d_out;

    cudaFuncSetAttribute(path_reward_collision_kernel,
                         cudaFuncAttributeMaxDynamicSharedMemorySize, SMEM_BYTES);
    path_reward_collision_kernel<<<NA, BLK, SMEM_BYTES>>>(
        targets, target_mask, traj_preds, agent_fut_width,
        other_trajs, other_masks, other_widths, out);
}

// round 15
// speedup vs baseline: 1.8514x; 1.0017x over previous
#include <cuda_runtime.h>

#define NA 256
#define NM 16
#define NT 80
#define NTH 40          // timesteps per CTA (t-half)
#define NO 64
#define OP 64           // candidate slot stride ([t][o], lane=o -> conflict-free)
#define PSTRIDE 18      // s_ptx row stride (floats): u64-aligned, 2-way write conflicts max
#define BLK 256

typedef unsigned long long u64;

// Per-(agent,half,mode) partials. Fully overwritten every launch -> deterministic.
__device__ float g_l2[NA * 2 * NM];
__device__ int   g_cnt[NA * 2 * NM];

static const int SMEM_BYTES = NTH * OP * 16 + 2 * NTH * PSTRIDE * 4;  // 40960+5760=46720

__device__ __forceinline__ u64 pk2(float lo, float hi) {
    u64 r; asm("mov.b64 %0, {%1, %2};" : "=l"(r) : "f"(lo), "f"(hi)); return r;
}
__device__ __forceinline__ u64 add2(u64 a, u64 b) {
    u64 r; asm("add.rn.f32x2 %0, %1, %2;" : "=l"(r) : "l"(a), "l"(b)); return r;
}
__device__ __forceinline__ u64 mul2(u64 a, u64 b) {
    u64 r; asm("mul.rn.f32x2 %0, %1, %2;" : "=l"(r) : "l"(a), "l"(b)); return r;
}

// Candidate slot: (-x, -y, -lo, r). Invalid -> all zeros (never hits, never bands).
__device__ __forceinline__ float4 make_cand(int mk, float x, float y, float hwi, float w) {
    if (mk > 0) {
        float r  = __fadd_rn(hwi, 0.5f * w);        // == 0.5*(w_i+w_o) bit-exactly
        float lo = __fmul_rn(__fmul_rn(r, r), 0.999996f);
        if (lo == 0.0f) lo = 1.401298464e-45f;      // r==0: hit iff d2==0
        return make_float4(-x, -y, -lo, r);
    }
    return make_float4(0.0f, 0.0f, 0.0f, 0.0f);
}

__global__ __launch_bounds__(BLK, 4) void k1_collision(
    const float* __restrict__ targets,          // (A,T,2)
    const int*   __restrict__ target_mask,      // (A,T)
    const float* __restrict__ traj_preds,       // (A,M,T,4)
    const float* __restrict__ agent_fut_width,  // (A,T)
    const float* __restrict__ other_trajs,      // (A,O,T,2)
    const int*   __restrict__ other_masks,      // (A,O,T)
    const float* __restrict__ other_widths)     // (A,O,T)
{
    extern __shared__ float4 s_o4[];            // [NTH][OP]
    float* s_ptx = (float*)(s_o4 + NTH * OP);   // [NTH][PSTRIDE] masked pred x
    float* s_pty = s_ptx + NTH * PSTRIDE;       // [NTH][PSTRIDE] masked pred y

    __shared__ float    s_tm[NTH], s_hwi[NTH], s_tgx[NTH], s_tgy[NTH], s_l2[NM];
    __shared__ int      s_vt[NTH];
    __shared__ int      s_nvt;
    __shared__ unsigned s_hit[NTH];

    const int blk  = blockIdx.x;
    const int a    = blk >> 1;
    const int half = blk & 1;
    const int t0   = half * NTH;
    const int tid  = threadIdx.x;
    const int wid  = tid >> 5, lane = tid & 31;

    // Ego per-timestep data.
    if (tid < NTH) {
        int t = tid;
        s_hit[t] = 0u;
        float tm = (float)target_mask[a * NT + t0 + t];
        s_tm[t]  = tm;
        s_hwi[t] = (tm > 0.0f) ? 0.5f * agent_fut_width[a * NT + t0 + t] : -1.0f;
        float2 tg = ((const float2*)targets)[a * NT + t0 + t];
        s_tgx[t] = __fmul_rn(tm, tg.x);
        s_tgy[t] = __fmul_rn(tm, tg.y);
    }
    __syncthreads();

    // Warp 0: sorted valid-t list via ballot scan.
    if (tid < 32) {
        int base = 0;
        #pragma unroll
        for (int k = 0; k < 2; k++) {
            int t = k * 32 + tid;
            bool v = (t < NTH) && (s_hwi[t] >= 0.0f);
            unsigned mk = __ballot_sync(0xffffffffu, v);
            if (v) s_vt[base + __popc(mk & ((1u << tid) - 1u))] = t;
            base += __popc(mk);
        }
        if (tid == 0) s_nvt = base;
    }

    // Masked preds -> SoA [t][m].
    {
        const float4* pb = (const float4*)traj_preds;
        #pragma unroll 1
        for (int i = tid; i < NM * NTH; i += BLK) {
            int m = i / NTH, t = i - m * NTH;
            float4 p = pb[(a * NM + m) * NT + t0 + t];
            float tm = s_tm[t];
            s_ptx[t * PSTRIDE + m] = __fmul_rn(tm, p.x);
            s_pty[t * PSTRIDE + m] = __fmul_rn(tm, p.y);
        }
    }

    // Candidates -> fixed slots [t][o], radius bounds folded.
    {
        const int4*   mkp = (const int4*)  (other_masks  + a * NO * NT);
        const float4* wdp = (const float4*)(other_widths + a * NO * NT);
        const float4* trp = (const float4*)(other_trajs  + 2 * a * NO * NT);
        const int hq = t0 >> 2, h2 = t0 >> 1;
        #pragma unroll 1
        for (int v = tid; v < NO * NTH / 4; v += BLK) {   // 640
            int o = v / (NTH / 4);
            int k = v - o * (NTH / 4);
            int4   mk  = mkp[o * (NT / 4) + hq + k];
            float4 wd  = wdp[o * (NT / 4) + hq + k];
            float4 xy0 = trp[o * (NT / 2) + h2 + 2 * k];
            float4 xy1 = trp[o * (NT / 2) + h2 + 2 * k + 1];
            int tl = 4 * k;
            s_o4[(tl + 0) * OP + o] = make_cand(mk.x, xy0.x, xy0.y, s_hwi[tl + 0], wd.x);
            s_o4[(tl + 1) * OP + o] = make_cand(mk.y, xy0.z, xy0.w, s_hwi[tl + 1], wd.y);
            s_o4[(tl + 2) * OP + o] = make_cand(mk.z, xy1.x, xy1.y, s_hwi[tl + 2], wd.z);
            s_o4[(tl + 3) * OP + o] = make_cand(mk.w, xy1.z, xy1.w, s_hwi[tl + 3], wd.w);
        }
    }
    __syncthreads();

    // L2 partial: warp w handles modes w, w+8; fixed-order shuffle tree.
    #pragma unroll 1
    for (int m = wid; m < NM; m += BLK / 32) {
        float acc = 0.0f;
        #pragma unroll
        for (int k = 0; k < 2; k++) {
            int t = lane + 32 * k;
            if (t < NTH) {
                float dx = __fsub_rn(s_ptx[t * PSTRIDE + m], s_tgx[t]);
                float dy = __fsub_rn(s_pty[t * PSTRIDE + m], s_tgy[t]);
                float s  = __fadd_rn(__fmul_rn(dx, dx), __fmul_rn(dy, dy));
                if (s > 0.0f) acc = __fadd_rn(acc, __fsqrt_rn(s));
            }
        }
        #pragma unroll
        for (int off = 16; off > 0; off >>= 1)
            acc = __fadd_rn(acc, __shfl_xor_sync(0xffffffffu, acc, off));
        if (lane == 0) s_l2[m] = acc;
    }

    // Collision: warp per valid t; lane owns candidates lane & lane+32.
    // Branchless packed-f32x2 certain/band test; rare exact slow path.
    {
        const u64 KHI = pk2(1.0000080f, 1.0000080f);
        const int nvt = s_nvt;
        #pragma unroll 1
        for (int v = wid; v < nvt; v += BLK / 32) {
            int t = s_vt[v];
            float4 c0 = s_o4[t * OP + lane];
            float4 c1 = s_o4[t * OP + 32 + lane];
            u64 nx0 = pk2(c0.x, c0.x), ny0 = pk2(c0.y, c0.y), nlo0 = pk2(c0.z, c0.z);
            u64 nx1 = pk2(c1.x, c1.x), ny1 = pk2(c1.y, c1.y), nlo1 = pk2(c1.z, c1.z);
            u64 nhi0 = mul2(nlo0, KHI), nhi1 = mul2(nlo1, KHI);
            const u64* pxp = (const u64*)(s_ptx + t * PSTRIDE);
            const u64* pyp = (const u64*)(s_pty + t * PSTRIDE);
            unsigned mask = 0;
            u64 flag = 0;
            #pragma unroll
            for (int p = 0; p < 8; p++) {
                u64 px = pxp[p], py = pyp[p];          // modes 2p, 2p+1 (broadcast)
                u64 dx0 = add2(px, nx0), dy0 = add2(py, ny0);
                u64 d20 = add2(mul2(dx0, dx0), mul2(dy0, dy0));
                u64 dx1 = add2(px, nx1), dy1 = add2(py, ny1);
                u64 d21 = add2(mul2(dx1, dx1), mul2(dy1, dy1));
                u64 sloC = add2(d20, nlo0) | add2(d21, nlo1);   // sign => certain hit
                flag |= (add2(d20, nhi0) | add2(d21, nhi1)) & ~sloC;  // sign => band
                unsigned l32 = (unsigned)sloC, h32 = (unsigned)(sloC >> 32);
                mask |= ((l32 >> 31) << (2 * p)) | ((h32 >> 31) << (2 * p + 1));
            }
            if (flag & 0x8000000080000000ULL) {
                // Exact re-evaluation of this lane's 32 tests (reference arithmetic).
                mask = 0;
                #pragma unroll 1
                for (int m = 0; m < NM; m++) {
                    float px = s_ptx[t * PSTRIDE + m];
                    float py = s_pty[t * PSTRIDE + m];
                    float dx = __fadd_rn(px, c0.x), dy = __fadd_rn(py, c0.y);
                    float d2 = __fadd_rn(__fmul_rn(dx, dx), __fmul_rn(dy, dy));
                    if (c0.z < 0.0f && __fsqrt_rn(d2) <= c0.w) mask |= 1u << m;
                    dx = __fadd_rn(px, c1.x); dy = __fadd_rn(py, c1.y);
                    d2 = __fadd_rn(__fmul_rn(dx, dx), __fmul_rn(dy, dy));
                    if (c1.z < 0.0f && __fsqrt_rn(d2) <= c1.w) mask |= 1u << m;
                }
            }
            mask = __reduce_or_sync(0xffffffffu, mask);
            if (lane == 0) s_hit[t] = mask;
        }
    }
    __syncthreads();

    // Per-half partials out (s_hit[t]=0 for invalid t, zeroed up front).
    if (tid < NM) {
        int cnt = 0;
        #pragma unroll
        for (int t = 0; t < NTH; t++) cnt += (int)((s_hit[t] >> tid) & 1u);
        int idx = (a * 2 + half) * NM + tid;
        g_cnt[idx] = cnt;
        g_l2[idx]  = s_l2[tid];
    }
}

__global__ __launch_bounds__(256) void k2_combine(float* __restrict__ out) {
    int i = blockIdx.x * 256 + threadIdx.x;
    if (i < NA * NM) {
        int a = i >> 4, m = i & 15;
        float l2sum = __fadd_rn(g_l2[(a * 2) * NM + m], g_l2[(a * 2 + 1) * NM + m]);
        int   cnt   = g_cnt[(a * 2) * NM + m] + g_cnt[(a * 2 + 1) * NM + m];
        float l2p = __fsub_rn(8.0f, l2sum);            // -(total_l2 - OFFSET)
        float cp  = __fmul_rn(-100.0f, (float)cnt);
        out[i]                = __fadd_rn(l2p, cp);    // total
        out[NA * NM + i]      = cp;                    // collision_penalty
        out[2 * NA * NM + i]  = l2p;                   // l2_penalty
    }
}

extern "C" void kernel_launch(void* const* d_in, const int* in_sizes, int n_in,
                              void* d_out, int out_size) {
    const float* targets         = (const float*)d_in[0];
    const int*   target_mask     = (const int*)  d_in[1];
    const float* traj_preds      = (const float*)d_in[2];
    // d_in[3] = mode_probs (unused by reference)
    const float* agent_fut_width = (const float*)d_in[4];
    const float* other_trajs     = (const float*)d_in[5];
    const int*   other_masks     = (const int*)  d_in[6];
    const float* other_widths    = (const float*)d_in[7];
    float* out = (float*)d_out;

    cudaFuncSetAttribute(k1_collision,
                         cudaFuncAttributeMaxDynamicSharedMemorySize, SMEM_BYTES);
    k1_collision<<<NA * 2, BLK, SMEM_BYTES>>>(
        targets, target_mask, traj_preds, agent_fut_width,
        other_trajs, other_masks, other_widths);
    k2_combine<<<(NA * NM + 255) / 256, 256>>>(out);
}

// round 16
// speedup vs baseline: 1.8765x; 1.0135x over previous
#include <cuda_runtime.h>

#define NA 256
#define NM 16
#define NT 80
#define NTH 40          // timesteps per CTA (t-half)
#define NO 64
#define OP 64           // candidate slot stride ([t][o], lane=o -> conflict-free)
#define PSTRIDE 18      // s_ptx row stride (floats): u64-aligned, 2-way write conflicts max
#define BLK 256

typedef unsigned long long u64;

// Per-(agent,half,mode) partials + per-agent ticket. Ticket self-resets each
// launch (combiner stores 0 after use) -> graph-replay safe & deterministic.
__device__ float g_l2[NA * 2 * NM];
__device__ int   g_cnt[NA * 2 * NM];
__device__ unsigned g_ticket[NA];

static const int SMEM_BYTES = NTH * OP * 16 + 2 * NTH * PSTRIDE * 4;  // 40960+5760=46720

__device__ __forceinline__ u64 pk2(float lo, float hi) {
    u64 r; asm("mov.b64 %0, {%1, %2};" : "=l"(r) : "f"(lo), "f"(hi)); return r;
}
__device__ __forceinline__ u64 add2(u64 a, u64 b) {
    u64 r; asm("add.rn.f32x2 %0, %1, %2;" : "=l"(r) : "l"(a), "l"(b)); return r;
}
__device__ __forceinline__ u64 mul2(u64 a, u64 b) {
    u64 r; asm("mul.rn.f32x2 %0, %1, %2;" : "=l"(r) : "l"(a), "l"(b)); return r;
}

// Candidate slot: (-x, -y, -lo, r). Invalid -> all zeros (never hits, never bands).
__device__ __forceinline__ float4 make_cand(int mk, float x, float y, float hwi, float w) {
    if (mk > 0) {
        float r  = __fadd_rn(hwi, 0.5f * w);        // == 0.5*(w_i+w_o) bit-exactly
        float lo = __fmul_rn(__fmul_rn(r, r), 0.999996f);
        if (lo == 0.0f) lo = 1.401298464e-45f;      // r==0: hit iff d2==0
        return make_float4(-x, -y, -lo, r);
    }
    return make_float4(0.0f, 0.0f, 0.0f, 0.0f);
}

__global__ __launch_bounds__(BLK, 4) void k1_collision(
    const float* __restrict__ targets,          // (A,T,2)
    const int*   __restrict__ target_mask,      // (A,T)
    const float* __restrict__ traj_preds,       // (A,M,T,4)
    const float* __restrict__ agent_fut_width,  // (A,T)
    const float* __restrict__ other_trajs,      // (A,O,T,2)
    const int*   __restrict__ other_masks,      // (A,O,T)
    const float* __restrict__ other_widths,     // (A,O,T)
    float*       __restrict__ out)              // (3,A,M)
{
    extern __shared__ float4 s_o4[];            // [NTH][OP]
    float* s_ptx = (float*)(s_o4 + NTH * OP);   // [NTH][PSTRIDE] masked pred x
    float* s_pty = s_ptx + NTH * PSTRIDE;       // [NTH][PSTRIDE] masked pred y

    __shared__ float    s_tm[NTH], s_hwi[NTH], s_tgx[NTH], s_tgy[NTH], s_l2[NM];
    __shared__ int      s_vt[NTH];
    __shared__ int      s_nvt;
    __shared__ unsigned s_hit[NTH];
    __shared__ unsigned s_ticket;

    const int blk  = blockIdx.x;
    const int a    = blk >> 1;
    const int half = blk & 1;
    const int t0   = half * NTH;
    const int tid  = threadIdx.x;
    const int wid  = tid >> 5, lane = tid & 31;

    // Ego per-timestep data.
    if (tid < NTH) {
        int t = tid;
        s_hit[t] = 0u;
        float tm = (float)target_mask[a * NT + t0 + t];
        s_tm[t]  = tm;
        s_hwi[t] = (tm > 0.0f) ? 0.5f * agent_fut_width[a * NT + t0 + t] : -1.0f;
        float2 tg = ((const float2*)targets)[a * NT + t0 + t];
        s_tgx[t] = __fmul_rn(tm, tg.x);
        s_tgy[t] = __fmul_rn(tm, tg.y);
    }
    __syncthreads();

    // Warp 0: sorted valid-t list via ballot scan.
    if (tid < 32) {
        int base = 0;
        #pragma unroll
        for (int k = 0; k < 2; k++) {
            int t = k * 32 + tid;
            bool v = (t < NTH) && (s_hwi[t] >= 0.0f);
            unsigned mk = __ballot_sync(0xffffffffu, v);
            if (v) s_vt[base + __popc(mk & ((1u << tid) - 1u))] = t;
            base += __popc(mk);
        }
        if (tid == 0) s_nvt = base;
    }

    // Masked preds -> SoA [t][m].
    {
        const float4* pb = (const float4*)traj_preds;
        #pragma unroll 1
        for (int i = tid; i < NM * NTH; i += BLK) {
            int m = i / NTH, t = i - m * NTH;
            float4 p = pb[(a * NM + m) * NT + t0 + t];
            float tm = s_tm[t];
            s_ptx[t * PSTRIDE + m] = __fmul_rn(tm, p.x);
            s_pty[t * PSTRIDE + m] = __fmul_rn(tm, p.y);
        }
    }

    // Candidates -> fixed slots [t][o], radius bounds folded.
    {
        const int4*   mkp = (const int4*)  (other_masks  + a * NO * NT);
        const float4* wdp = (const float4*)(other_widths + a * NO * NT);
        const float4* trp = (const float4*)(other_trajs  + 2 * a * NO * NT);
        const int hq = t0 >> 2, h2 = t0 >> 1;
        #pragma unroll 1
        for (int v = tid; v < NO * NTH / 4; v += BLK) {   // 640
            int o = v / (NTH / 4);
            int k = v - o * (NTH / 4);
            int4   mk  = mkp[o * (NT / 4) + hq + k];
            float4 wd  = wdp[o * (NT / 4) + hq + k];
            float4 xy0 = trp[o * (NT / 2) + h2 + 2 * k];
            float4 xy1 = trp[o * (NT / 2) + h2 + 2 * k + 1];
            int tl = 4 * k;
            s_o4[(tl + 0) * OP + o] = make_cand(mk.x, xy0.x, xy0.y, s_hwi[tl + 0], wd.x);
            s_o4[(tl + 1) * OP + o] = make_cand(mk.y, xy0.z, xy0.w, s_hwi[tl + 1], wd.y);
            s_o4[(tl + 2) * OP + o] = make_cand(mk.z, xy1.x, xy1.y, s_hwi[tl + 2], wd.z);
            s_o4[(tl + 3) * OP + o] = make_cand(mk.w, xy1.z, xy1.w, s_hwi[tl + 3], wd.w);
        }
    }
    __syncthreads();

    // L2 partial: warp w handles modes w, w+8; fixed-order shuffle tree.
    #pragma unroll 1
    for (int m = wid; m < NM; m += BLK / 32) {
        float acc = 0.0f;
        #pragma unroll
        for (int k = 0; k < 2; k++) {
            int t = lane + 32 * k;
            if (t < NTH) {
                float dx = __fsub_rn(s_ptx[t * PSTRIDE + m], s_tgx[t]);
                float dy = __fsub_rn(s_pty[t * PSTRIDE + m], s_tgy[t]);
                float s  = __fadd_rn(__fmul_rn(dx, dx), __fmul_rn(dy, dy));
                if (s > 0.0f) acc = __fadd_rn(acc, __fsqrt_rn(s));
            }
        }
        #pragma unroll
        for (int off = 16; off > 0; off >>= 1)
            acc = __fadd_rn(acc, __shfl_xor_sync(0xffffffffu, acc, off));
        if (lane == 0) s_l2[m] = acc;
    }

    // Collision: warp per valid t; lane owns candidates lane & lane+32.
    // Branchless packed-f32x2 certain/band test; rare exact slow path.
    {
        const u64 KHI = pk2(1.0000080f, 1.0000080f);
        const int nvt = s_nvt;
        #pragma unroll 1
        for (int v = wid; v < nvt; v += BLK / 32) {
            int t = s_vt[v];
            float4 c0 = s_o4[t * OP + lane];
            float4 c1 = s_o4[t * OP + 32 + lane];
            u64 nx0 = pk2(c0.x, c0.x), ny0 = pk2(c0.y, c0.y), nlo0 = pk2(c0.z, c0.z);
            u64 nx1 = pk2(c1.x, c1.x), ny1 = pk2(c1.y, c1.y), nlo1 = pk2(c1.z, c1.z);
            u64 nhi0 = mul2(nlo0, KHI), nhi1 = mul2(nlo1, KHI);
            const u64* pxp = (const u64*)(s_ptx + t * PSTRIDE);
            const u64* pyp = (const u64*)(s_pty + t * PSTRIDE);
            unsigned mask = 0;
            u64 flag = 0;
            #pragma unroll
            for (int p = 0; p < 8; p++) {
                u64 px = pxp[p], py = pyp[p];          // modes 2p, 2p+1 (broadcast)
                u64 dx0 = add2(px, nx0), dy0 = add2(py, ny0);
                u64 d20 = add2(mul2(dx0, dx0), mul2(dy0, dy0));
                u64 dx1 = add2(px, nx1), dy1 = add2(py, ny1);
                u64 d21 = add2(mul2(dx1, dx1), mul2(dy1, dy1));
                u64 sloC = add2(d20, nlo0) | add2(d21, nlo1);   // sign => certain hit
                flag |= (add2(d20, nhi0) | add2(d21, nhi1)) & ~sloC;  // sign => band
                unsigned l32 = (unsigned)sloC, h32 = (unsigned)(sloC >> 32);
                mask |= ((l32 >> 31) << (2 * p)) | ((h32 >> 31) << (2 * p + 1));
            }
            if (flag & 0x8000000080000000ULL) {
                // Exact re-evaluation of this lane's 32 tests (reference arithmetic).
                mask = 0;
                #pragma unroll 1
                for (int m = 0; m < NM; m++) {
                    float px = s_ptx[t * PSTRIDE + m];
                    float py = s_pty[t * PSTRIDE + m];
                    float dx = __fadd_rn(px, c0.x), dy = __fadd_rn(py, c0.y);
                    float d2 = __fadd_rn(__fmul_rn(dx, dx), __fmul_rn(dy, dy));
                    if (c0.z < 0.0f && __fsqrt_rn(d2) <= c0.w) mask |= 1u << m;
                    dx = __fadd_rn(px, c1.x); dy = __fadd_rn(py, c1.y);
                    d2 = __fadd_rn(__fmul_rn(dx, dx), __fmul_rn(dy, dy));
                    if (c1.z < 0.0f && __fsqrt_rn(d2) <= c1.w) mask |= 1u << m;
                }
            }
            mask = __reduce_or_sync(0xffffffffu, mask);
            if (lane == 0) s_hit[t] = mask;
        }
    }
    __syncthreads();

    // Write this half's partials; local copies kept in registers.
    int   my_cnt = 0;
    float my_l2  = 0.0f;
    if (tid < NM) {
        #pragma unroll
        for (int t = 0; t < NTH; t++) my_cnt += (int)((s_hit[t] >> tid) & 1u);
        my_l2 = s_l2[tid];
        int idx = (a * 2 + half) * NM + tid;
        g_cnt[idx] = my_cnt;
        g_l2[idx]  = my_l2;
    }
    __syncthreads();

    // Ticket: the second CTA of this agent combines (threadfence-reduction pattern).
    if (tid == 0) {
        __threadfence();                               // partials visible before ticket
        s_ticket = atomicAdd(&g_ticket[a], 1u);
    }
    __syncthreads();

    if (s_ticket == 1u) {
        if (tid < NM) {
            __threadfence();                           // order peer-partial loads
            int peer = (a * 2 + (half ^ 1)) * NM + tid;
            float pl2  = *((volatile float*)&g_l2[peer]);
            int   pcnt = *((volatile int*)&g_cnt[peer]);
            // Fixed association: half0 + half1 regardless of which CTA combines.
            float l2sum = half ? __fadd_rn(pl2, my_l2) : __fadd_rn(my_l2, pl2);
            int   cnt   = my_cnt + pcnt;
            float l2p = __fsub_rn(8.0f, l2sum);        // -(total_l2 - OFFSET)
            float cp  = __fmul_rn(-100.0f, (float)cnt);
            int i = a * NM + tid;
            out[i]               = __fadd_rn(l2p, cp); // total
            out[NA * NM + i]     = cp;                 // collision_penalty
            out[2 * NA * NM + i] = l2p;                // l2_penalty
        }
        if (tid == 0) g_ticket[a] = 0u;                // reset for next (graph) launch
    }
}

extern "C" void kernel_launch(void* const* d_in, const int* in_sizes, int n_in,
                              void* d_out, int out_size) {
    const float* targets         = (const float*)d_in[0];
    const int*   target_mask     = (const int*)  d_in[1];
    const float* traj_preds      = (const float*)d_in[2];
    // d_in[3] = mode_probs (unused by reference)
    const float* agent_fut_width = (const float*)d_in[4];
    const float* other_trajs     = (const float*)d_in[5];
    const int*   other_masks     = (const int*)  d_in[6];
    const float* other_widths    = (const float*)d_in[7];
    float* out = (float*)d_out;

    cudaFuncSetAttribute(k1_collision,
                         cudaFuncAttributeMaxDynamicSharedMemorySize, SMEM_BYTES);
    k1_collision<<<NA * 2, BLK, SMEM_BYTES>>>(
        targets, target_mask, traj_preds, agent_fut_width,
        other_trajs, other_masks, other_widths, out);
}

// round 17
// speedup vs baseline: 2.0690x; 1.1026x over previous
#include <cuda_runtime.h>

#define NA 256
#define NM 16
#define NT 80
#define NTH 40          // timesteps per CTA (t-half)
#define NTQ 10          // NTH/4
#define NO 64
#define OP 65           // candidate row stride in elems (bank-staggered)
#define PSTRIDE 18      // pred SoA row stride (floats)
#define BLK 256

typedef unsigned long long u64;

// Per-(agent,half,mode) partials + per-agent ticket (self-resetting).
__device__ float g_l2[NA * 2 * NM];
__device__ int   g_cnt[NA * 2 * NM];
__device__ unsigned g_ticket[NA];

// Dynamic smem: cxy float2[NTH*OP], cw float[NTH*OP], ptx/pty float[NTH*PSTRIDE]
static const int SMEM_BYTES = NTH * OP * 8 + NTH * OP * 4 + 2 * NTH * PSTRIDE * 4; // 36960

__device__ __forceinline__ u64 pk2(float lo, float hi) {
    u64 r; asm("mov.b64 %0, {%1, %2};" : "=l"(r) : "f"(lo), "f"(hi)); return r;
}
__device__ __forceinline__ u64 add2(u64 a, u64 b) {
    u64 r; asm("add.rn.f32x2 %0, %1, %2;" : "=l"(r) : "l"(a), "l"(b)); return r;
}
__device__ __forceinline__ u64 mul2(u64 a, u64 b) {
    u64 r; asm("mul.rn.f32x2 %0, %1, %2;" : "=l"(r) : "l"(a), "l"(b)); return r;
}

__global__ __launch_bounds__(BLK, 3) void k1_collision(
    const float* __restrict__ targets,          // (A,T,2)
    const int*   __restrict__ target_mask,      // (A,T)
    const float* __restrict__ traj_preds,       // (A,M,T,4)
    const float* __restrict__ agent_fut_width,  // (A,T)
    const float* __restrict__ other_trajs,      // (A,O,T,2)
    const int*   __restrict__ other_masks,      // (A,O,T)
    const float* __restrict__ other_widths,     // (A,O,T)
    float*       __restrict__ out)              // (3,A,M)
{
    extern __shared__ float2 s_cxy[];           // [NTH][OP]  (-x, -y)
    float* s_cw  = (float*)(s_cxy + NTH * OP);  // [NTH][OP]  0.5*w_o | -1e30
    float* s_ptx = s_cw + NTH * OP;             // [NTH][PSTRIDE] raw pred x
    float* s_pty = s_ptx + NTH * PSTRIDE;       // [NTH][PSTRIDE] raw pred y

    __shared__ float    s_hwi[NTH], s_tgx[NTH], s_tgy[NTH], s_l2[NM];
    __shared__ int      s_vt[NTH];
    __shared__ int      s_nvt;
    __shared__ unsigned s_hit[NTH];
    __shared__ unsigned s_ticket;

    const int blk  = blockIdx.x;
    const int a    = blk >> 1;
    const int half = blk & 1;
    const int t0   = half * NTH;
    const int tid  = threadIdx.x;
    const int wid  = tid >> 5, lane = tid & 31;

    // ---------- Front-batched load phase (no barriers, max MLP) ----------
    const int hq = t0 >> 2, h2 = t0 >> 1;
    const int4*   mkp = (const int4*)  (other_masks  + a * NO * NT);
    const float4* wdp = (const float4*)(other_widths + a * NO * NT);
    const float4* trp = (const float4*)(other_trajs  + 2 * a * NO * NT);
    const float4* pb  = (const float4*)traj_preds;

    // Candidate tasks v0, v1 (all threads) and v2 (tid<128). o slow, k fast -> coalesced.
    const int v0 = tid, v1 = tid + BLK, v2 = tid + 2 * BLK;
    const int o0 = v0 / NTQ, k0 = v0 - o0 * NTQ;
    const int o1 = v1 / NTQ, k1 = v1 - o1 * NTQ;
    const int o2 = v2 / NTQ, k2 = v2 - o2 * NTQ;
    int4   mk0 = mkp[o0 * (NT / 4) + hq + k0];
    float4 wd0 = wdp[o0 * (NT / 4) + hq + k0];
    float4 A0  = trp[o0 * (NT / 2) + h2 + 2 * k0];
    float4 B0  = trp[o0 * (NT / 2) + h2 + 2 * k0 + 1];
    int4   mk1 = mkp[o1 * (NT / 4) + hq + k1];
    float4 wd1 = wdp[o1 * (NT / 4) + hq + k1];
    float4 A1  = trp[o1 * (NT / 2) + h2 + 2 * k1];
    float4 B1  = trp[o1 * (NT / 2) + h2 + 2 * k1 + 1];
    // Pred tasks i0, i1 (all threads), i2 (tid<128).
    const int i0 = tid, i1 = tid + BLK, i2 = tid + 2 * BLK;
    const int m0 = i0 / NTH, pt0 = i0 - m0 * NTH;
    const int m1 = i1 / NTH, pt1 = i1 - m1 * NTH;
    const int m2 = i2 / NTH, pt2 = i2 - m2 * NTH;
    float4 p0 = pb[(a * NM + m0) * NT + t0 + pt0];
    float4 p1 = pb[(a * NM + m1) * NT + t0 + pt1];

    // Ego loads (tid < NTH).
    int   ego_mk = 0; float ego_w = 0.0f; float2 ego_tg = make_float2(0.f, 0.f);
    if (tid < NTH) {
        ego_mk = target_mask[a * NT + t0 + tid];
        ego_w  = agent_fut_width[a * NT + t0 + tid];
        ego_tg = ((const float2*)targets)[a * NT + t0 + tid];
        s_hit[tid] = 0u;
    }
    // Tail tasks (tid < 128).
    int4 mk2; float4 wd2, A2, B2, p2;
    if (tid < NO * NTH / 4 - 2 * BLK) {
        mk2 = mkp[o2 * (NT / 4) + hq + k2];
        wd2 = wdp[o2 * (NT / 4) + hq + k2];
        A2  = trp[o2 * (NT / 2) + h2 + 2 * k2];
        B2  = trp[o2 * (NT / 2) + h2 + 2 * k2 + 1];
        p2  = pb[(a * NM + m2) * NT + t0 + pt2];
    }

    // ---------- Stores (pure transposes) ----------
    #define CSTORE(oo, kk, jj, mkc, wc, xx, yy) do {                          \
        int idx = (4 * (kk) + (jj)) * OP + (oo);                              \
        s_cxy[idx] = make_float2(-(xx), -(yy));                               \
        s_cw[idx]  = ((mkc) > 0) ? 0.5f * (wc) : -1e30f;                      \
    } while (0)

    CSTORE(o0, k0, 0, mk0.x, wd0.x, A0.x, A0.y);
    CSTORE(o0, k0, 1, mk0.y, wd0.y, A0.z, A0.w);
    CSTORE(o0, k0, 2, mk0.z, wd0.z, B0.x, B0.y);
    CSTORE(o0, k0, 3, mk0.w, wd0.w, B0.z, B0.w);
    CSTORE(o1, k1, 0, mk1.x, wd1.x, A1.x, A1.y);
    CSTORE(o1, k1, 1, mk1.y, wd1.y, A1.z, A1.w);
    CSTORE(o1, k1, 2, mk1.z, wd1.z, B1.x, B1.y);
    CSTORE(o1, k1, 3, mk1.w, wd1.w, B1.z, B1.w);
    s_ptx[pt0 * PSTRIDE + m0] = p0.x;  s_pty[pt0 * PSTRIDE + m0] = p0.y;
    s_ptx[pt1 * PSTRIDE + m1] = p1.x;  s_pty[pt1 * PSTRIDE + m1] = p1.y;
    if (tid < NTH) {
        s_hwi[tid] = (ego_mk > 0) ? 0.5f * ego_w : -1.0f;
        s_tgx[tid] = ego_tg.x;
        s_tgy[tid] = ego_tg.y;
    }
    if (tid < NO * NTH / 4 - 2 * BLK) {
        CSTORE(o2, k2, 0, mk2.x, wd2.x, A2.x, A2.y);
        CSTORE(o2, k2, 1, mk2.y, wd2.y, A2.z, A2.w);
        CSTORE(o2, k2, 2, mk2.z, wd2.z, B2.x, B2.y);
        CSTORE(o2, k2, 3, mk2.w, wd2.w, B2.z, B2.w);
        s_ptx[pt2 * PSTRIDE + m2] = p2.x;  s_pty[pt2 * PSTRIDE + m2] = p2.y;
    }
    __syncthreads();

    // Warp 0: sorted valid-t list via ballot scan.
    if (tid < 32) {
        int base = 0;
        #pragma unroll
        for (int k = 0; k < 2; k++) {
            int t = k * 32 + tid;
            bool v = (t < NTH) && (s_hwi[t] >= 0.0f);
            unsigned mk = __ballot_sync(0xffffffffu, v);
            if (v) s_vt[base + __popc(mk & ((1u << tid) - 1u))] = t;
            base += __popc(mk);
        }
        if (tid == 0) s_nvt = base;
    }

    // L2 partial: warp w handles modes w, w+8; only valid t contribute (raw preds).
    #pragma unroll 1
    for (int m = wid; m < NM; m += BLK / 32) {
        float acc = 0.0f;
        #pragma unroll
        for (int k = 0; k < 2; k++) {
            int t = lane + 32 * k;
            if (t < NTH && s_hwi[t] >= 0.0f) {
                float dx = __fsub_rn(s_ptx[t * PSTRIDE + m], s_tgx[t]);
                float dy = __fsub_rn(s_pty[t * PSTRIDE + m], s_tgy[t]);
                float s  = __fadd_rn(__fmul_rn(dx, dx), __fmul_rn(dy, dy));
                if (s > 0.0f) acc = __fadd_rn(acc, __fsqrt_rn(s));
            }
        }
        #pragma unroll
        for (int off = 16; off > 0; off >>= 1)
            acc = __fadd_rn(acc, __shfl_xor_sync(0xffffffffu, acc, off));
        if (lane == 0) s_l2[m] = acc;
    }
    __syncthreads();   // s_vt/s_nvt ready (also covers warp0's list build)

    // Collision: warp per valid t; lane owns candidates lane & lane+32.
    // Radius bounds computed in registers (amortized over 16 modes).
    {
        const int nvt = s_nvt;
        #pragma unroll 1
        for (int v = wid; v < nvt; v += BLK / 32) {
            int t = s_vt[v];
            float hwi = s_hwi[t];
            float2 c0 = s_cxy[t * OP + lane];
            float2 c1 = s_cxy[t * OP + 32 + lane];
            float w0 = s_cw[t * OP + lane];
            float w1 = s_cw[t * OP + 32 + lane];
            float r0 = __fadd_rn(hwi, w0);               // bit-exact reference radius
            float r1 = __fadd_rn(hwi, w1);
            // nlo = -(r*|r|*0.999996): +INF for invalid (r<0 large), clamp r==0.
            float nlo0f = __fmul_rn(__fmul_rn(r0, fabsf(r0)), -0.999996f);
            float nlo1f = __fmul_rn(__fmul_rn(r1, fabsf(r1)), -0.999996f);
            if (nlo0f == 0.0f) nlo0f = -1.401298464e-45f;
            if (nlo1f == 0.0f) nlo1f = -1.401298464e-45f;
            u64 nx0 = pk2(c0.x, c0.x), ny0 = pk2(c0.y, c0.y), nlo0 = pk2(nlo0f, nlo0f);
            u64 nx1 = pk2(c1.x, c1.x), ny1 = pk2(c1.y, c1.y), nlo1 = pk2(nlo1f, nlo1f);
            u64 nhi0 = mul2(nlo0, pk2(1.0000080f, 1.0000080f));
            u64 nhi1 = mul2(nlo1, pk2(1.0000080f, 1.0000080f));
            const u64* pxp = (const u64*)(s_ptx + t * PSTRIDE);
            const u64* pyp = (const u64*)(s_pty + t * PSTRIDE);
            unsigned mask = 0;
            u64 flag = 0;
            #pragma unroll
            for (int p = 0; p < 8; p++) {
                u64 px = pxp[p], py = pyp[p];          // modes 2p, 2p+1 (broadcast)
                u64 dx0 = add2(px, nx0), dy0 = add2(py, ny0);
                u64 d20 = add2(mul2(dx0, dx0), mul2(dy0, dy0));
                u64 dx1 = add2(px, nx1), dy1 = add2(py, ny1);
                u64 d21 = add2(mul2(dx1, dx1), mul2(dy1, dy1));
                u64 sloC = add2(d20, nlo0) | add2(d21, nlo1);   // sign => certain hit
                flag |= (add2(d20, nhi0) | add2(d21, nhi1)) & ~sloC;  // sign => band
                unsigned l32 = (unsigned)sloC, h32 = (unsigned)(sloC >> 32);
                mask |= ((l32 >> 31) << (2 * p)) | ((h32 >> 31) << (2 * p + 1));
            }
            if (flag & 0x8000000080000000ULL) {
                // Exact re-evaluation of this lane's 32 tests (reference arithmetic).
                mask = 0;
                #pragma unroll 1
                for (int m = 0; m < NM; m++) {
                    float px = s_ptx[t * PSTRIDE + m];
                    float py = s_pty[t * PSTRIDE + m];
                    float dx = __fadd_rn(px, c0.x), dy = __fadd_rn(py, c0.y);
                    float d2 = __fadd_rn(__fmul_rn(dx, dx), __fmul_rn(dy, dy));
                    if (r0 >= 0.0f && __fsqrt_rn(d2) <= r0) mask |= 1u << m;
                    dx = __fadd_rn(px, c1.x); dy = __fadd_rn(py, c1.y);
                    d2 = __fadd_rn(__fmul_rn(dx, dx), __fmul_rn(dy, dy));
                    if (r1 >= 0.0f && __fsqrt_rn(d2) <= r1) mask |= 1u << m;
                }
            }
            mask = __reduce_or_sync(0xffffffffu, mask);
            if (lane == 0) s_hit[t] = mask;
        }
    }
    __syncthreads();

    // Write this half's partials; local copies kept in registers.
    int   my_cnt = 0;
    float my_l2  = 0.0f;
    if (tid < NM) {
        #pragma unroll
        for (int t = 0; t < NTH; t++) my_cnt += (int)((s_hit[t] >> tid) & 1u);
        my_l2 = s_l2[tid];
        int idx = (a * 2 + half) * NM + tid;
        g_cnt[idx] = my_cnt;
        g_l2[idx]  = my_l2;
    }
    __syncthreads();

    // Ticket: the second CTA of this agent combines (threadfence-reduction).
    if (tid == 0) {
        __threadfence();
        s_ticket = atomicAdd(&g_ticket[a], 1u);
    }
    __syncthreads();

    if (s_ticket == 1u) {
        if (tid < NM) {
            __threadfence();
            int peer = (a * 2 + (half ^ 1)) * NM + tid;
            float pl2  = *((volatile float*)&g_l2[peer]);
            int   pcnt = *((volatile int*)&g_cnt[peer]);
            float l2sum = half ? __fadd_rn(pl2, my_l2) : __fadd_rn(my_l2, pl2);
            int   cnt   = my_cnt + pcnt;
            float l2p = __fsub_rn(8.0f, l2sum);        // -(total_l2 - OFFSET)
            float cp  = __fmul_rn(-100.0f, (float)cnt);
            int i = a * NM + tid;
            out[i]               = __fadd_rn(l2p, cp); // total
            out[NA * NM + i]     = cp;                 // collision_penalty
            out[2 * NA * NM + i] = l2p;                // l2_penalty
        }
        if (tid == 0) g_ticket[a] = 0u;                // reset for next launch
    }
}

extern "C" void kernel_launch(void* const* d_in, const int* in_sizes, int n_in,
                              void* d_out, int out_size) {
    const float* targets         = (const float*)d_in[0];
    const int*   target_mask     = (const int*)  d_in[1];
    const float* traj_preds      = (const float*)d_in[2];
    // d_in[3] = mode_probs (unused by reference)
    const float* agent_fut_width = (const float*)d_in[4];
    const float* other_trajs     = (const float*)d_in[5];
    const int*   other_masks     = (const int*)  d_in[6];
    const float* other_widths    = (const float*)d_in[7];
    float* out = (float*)d_out;

    cudaFuncSetAttribute(k1_collision,
                         cudaFuncAttributeMaxDynamicSharedMemorySize, SMEM_BYTES);
    k1_collision<<<NA * 2, BLK, SMEM_BYTES>>>(
        targets, target_mask, traj_preds, agent_fut_width,
        other_trajs, other_masks, other_widths, out);
}